// round 8
// baseline (speedup 1.0000x reference)
#include <cuda_runtime.h>
#include <cuda_bf16.h>
#include <cstdint>
#include <cstddef>

#define N_NODES 50000
#define DIM_IN  256
#define DIM_HID 256
#define DIM_OUT 128
#define N_HEADS 4
#define E_MAX   800000

// ---------------- scratch -----------------------------------------------------
__device__ float g_xw0 [N_NODES * DIM_HID];
__device__ float g_xw1 [N_NODES * DIM_OUT];
__device__ float g_als0[N_NODES * N_HEADS];
__device__ float g_ald0[N_NODES * N_HEADS];
__device__ float g_als1[N_NODES];
__device__ float g_ald1[N_NODES];

// CSR by destination
__device__ int g_deg   [N_NODES];
__device__ int g_off   [N_NODES];
__device__ int g_cursor[N_NODES];
__device__ int g_csrc  [E_MAX];

// bf16 hi/lo splits
__device__ __nv_bfloat16 g_hhi [N_NODES * DIM_HID];
__device__ __nv_bfloat16 g_hlo [N_NODES * DIM_HID];
__device__ __nv_bfloat16 g_h1hi[N_NODES * DIM_HID];
__device__ __nv_bfloat16 g_h1lo[N_NODES * DIM_HID];
__device__ __nv_bfloat16 g_h2hi[N_NODES * DIM_OUT];
__device__ __nv_bfloat16 g_h2lo[N_NODES * DIM_OUT];
// transposed weights [N][K]
__device__ __nv_bfloat16 g_WpThi[DIM_HID * DIM_IN];
__device__ __nv_bfloat16 g_WpTlo[DIM_HID * DIM_IN];
__device__ __nv_bfloat16 g_W0Thi[DIM_HID * DIM_HID];
__device__ __nv_bfloat16 g_W0Tlo[DIM_HID * DIM_HID];
__device__ __nv_bfloat16 g_W1Thi[DIM_OUT * DIM_HID];
__device__ __nv_bfloat16 g_W1Tlo[DIM_OUT * DIM_HID];
__device__ __nv_bfloat16 g_WoThi[DIM_OUT * DIM_OUT];
__device__ __nv_bfloat16 g_WoTlo[DIM_OUT * DIM_OUT];

// ---------------- helpers ------------------------------------------------------
__device__ __forceinline__ float lrelu(float v) { return v > 0.0f ? v : 0.2f * v; }

__device__ __forceinline__ void split2(float a, float b, uint32_t& hi, uint32_t& lo) {
    __nv_bfloat16 ah = __float2bfloat16(a), bh = __float2bfloat16(b);
    __nv_bfloat16 al = __float2bfloat16(a - __bfloat162float(ah));
    __nv_bfloat16 bl = __float2bfloat16(b - __bfloat162float(bh));
    hi = (uint32_t)__bfloat16_as_ushort(ah) | ((uint32_t)__bfloat16_as_ushort(bh) << 16);
    lo = (uint32_t)__bfloat16_as_ushort(al) | ((uint32_t)__bfloat16_as_ushort(bl) << 16);
}

__device__ __forceinline__ float2 bf2_to_f2(uint32_t u) {
    __nv_bfloat162 t = *reinterpret_cast<__nv_bfloat162*>(&u);
    return make_float2(__bfloat162float(t.x), __bfloat162float(t.y));
}

__device__ __forceinline__ uint32_t smem_u32(const void* p) {
    uint32_t a;
    asm("{ .reg .u64 t; cvta.to.shared.u64 t, %1; cvt.u32.u64 %0, t; }" : "=r"(a) : "l"(p));
    return a;
}
__device__ __forceinline__ void cp_async16(uint32_t dst, const void* src) {
    asm volatile("cp.async.cg.shared.global [%0], [%1], 16;" :: "r"(dst), "l"(src));
}
#define CP_COMMIT()  asm volatile("cp.async.commit_group;" ::: "memory")
#define CP_WAIT0()   asm volatile("cp.async.wait_group 0;" ::: "memory")

__device__ __forceinline__ void ldsm_x4(uint32_t& r0, uint32_t& r1, uint32_t& r2, uint32_t& r3,
                                        uint32_t addr) {
    asm volatile("ldmatrix.sync.aligned.m8n8.x4.shared.b16 {%0,%1,%2,%3}, [%4];"
                 : "=r"(r0), "=r"(r1), "=r"(r2), "=r"(r3) : "r"(addr));
}

#define MMA_BF16(d, a0, a1, a2, a3, b0, b1) \
    asm volatile("mma.sync.aligned.m16n8k16.row.col.f32.bf16.bf16.f32 " \
                 "{%0,%1,%2,%3},{%4,%5,%6,%7},{%8,%9},{%0,%1,%2,%3};" \
                 : "+f"((d).x), "+f"((d).y), "+f"((d).z), "+f"((d).w) \
                 : "r"(a0), "r"(a1), "r"(a2), "r"(a3), "r"(b0), "r"(b1))

// ---------------- prep: weight transpose+split ----------------------------------
__global__ void tsplit_all_kernel(
    const float* __restrict__ Wp, __nv_bfloat16* __restrict__ WpThi, __nv_bfloat16* __restrict__ WpTlo,
    const float* __restrict__ W0, __nv_bfloat16* __restrict__ W0Thi, __nv_bfloat16* __restrict__ W0Tlo,
    const float* __restrict__ W1, __nv_bfloat16* __restrict__ W1Thi, __nv_bfloat16* __restrict__ W1Tlo,
    const float* __restrict__ Wo, __nv_bfloat16* __restrict__ WoThi, __nv_bfloat16* __restrict__ WoTlo)
{
    const int S0 = DIM_IN * DIM_HID;
    const int S1 = S0 + DIM_HID * DIM_HID;
    const int S2 = S1 + DIM_HID * DIM_OUT;
    const int S3 = S2 + DIM_OUT * DIM_OUT;
    int gi = blockIdx.x * blockDim.x + threadIdx.x;
    if (gi >= S3) return;
    const float* W; __nv_bfloat16* Thi; __nv_bfloat16* Tlo; int K, N, idx;
    if (gi < S0)      { W = Wp; Thi = WpThi; Tlo = WpTlo; K = DIM_IN;  N = DIM_HID; idx = gi; }
    else if (gi < S1) { W = W0; Thi = W0Thi; Tlo = W0Tlo; K = DIM_HID; N = DIM_HID; idx = gi - S0; }
    else if (gi < S2) { W = W1; Thi = W1Thi; Tlo = W1Tlo; K = DIM_HID; N = DIM_OUT; idx = gi - S1; }
    else              { W = Wo; Thi = WoThi; Tlo = WoTlo; K = DIM_OUT; N = DIM_OUT; idx = gi - S2; }
    int k = idx / N, nn = idx % N;
    float v = W[idx];
    __nv_bfloat16 h = __float2bfloat16(v);
    __nv_bfloat16 l = __float2bfloat16(v - __bfloat162float(h));
    Thi[(size_t)nn * K + k] = h;
    Tlo[(size_t)nn * K + k] = l;
}

// ---------------- CSR build ------------------------------------------------------
__global__ void zero_kernel(int* __restrict__ p, int n)
{
    int i = blockIdx.x * blockDim.x + threadIdx.x;
    if (i < n) p[i] = 0;
}

__global__ void hist_kernel(const int* __restrict__ dst, int* __restrict__ deg, int E)
{
    int i = blockIdx.x * blockDim.x + threadIdx.x;
    int e4 = E >> 2;
    if (i < e4) {
        int4 d = ((const int4*)dst)[i];
        atomicAdd(&deg[d.x], 1);
        atomicAdd(&deg[d.y], 1);
        atomicAdd(&deg[d.z], 1);
        atomicAdd(&deg[d.w], 1);
    } else if (i == e4) {
        for (int t = e4 * 4; t < E; t++) atomicAdd(&deg[dst[t]], 1);
    }
}

__global__ void scan_kernel(const int* __restrict__ deg, int* __restrict__ off,
                            int* __restrict__ cursor, int n)
{
    __shared__ int wsum[32];
    __shared__ int carry_sh;
    const int tid = threadIdx.x;
    const int lane = tid & 31;
    const int wid = tid >> 5;
    if (tid == 0) carry_sh = 0;
    __syncthreads();
    for (int base = 0; base < n; base += 1024) {
        int i = base + tid;
        int v = (i < n) ? deg[i] : 0;
        int x = v;
        #pragma unroll
        for (int o = 1; o < 32; o <<= 1) {
            int t = __shfl_up_sync(0xffffffffu, x, o);
            if (lane >= o) x += t;
        }
        if (lane == 31) wsum[wid] = x;
        __syncthreads();
        if (wid == 0) {
            int s = wsum[lane];
            #pragma unroll
            for (int o = 1; o < 32; o <<= 1) {
                int t = __shfl_up_sync(0xffffffffu, s, o);
                if (lane >= o) s += t;
            }
            wsum[lane] = s;
        }
        __syncthreads();
        int warpoff = (wid > 0) ? wsum[wid - 1] : 0;
        int excl = x - v + warpoff + carry_sh;
        if (i < n) { off[i] = excl; cursor[i] = excl; }
        __syncthreads();
        if (tid == 0) carry_sh += wsum[31];
        __syncthreads();
    }
}

__global__ void scatter_kernel(const int* __restrict__ src, const int* __restrict__ dst,
                               int* __restrict__ cursor, int* __restrict__ csrc, int E)
{
    int i = blockIdx.x * blockDim.x + threadIdx.x;
    int e4 = E >> 2;
    if (i < e4) {
        int4 s = ((const int4*)src)[i];
        int4 d = ((const int4*)dst)[i];
        csrc[atomicAdd(&cursor[d.x], 1)] = s.x;
        csrc[atomicAdd(&cursor[d.y], 1)] = s.y;
        csrc[atomicAdd(&cursor[d.z], 1)] = s.z;
        csrc[atomicAdd(&cursor[d.w], 1)] = s.w;
    } else if (i == e4) {
        for (int t = e4 * 4; t < E; t++)
            csrc[atomicAdd(&cursor[dst[t]], 1)] = src[t];
    }
}

// ---------------- mma.sync split-precision GEMM, BM=128, BN=NTILE (full), BK=64 --
// 512 threads, 16 warps in 4(M)x4(N) grid. grid.x = 1 (A read exactly once).
// EPI: 3 relu(+bias) -> bf16 hi/lo only
//      4 fp32 C + fused multi-head logits (head = 64-col block)
//      5 fp32 C + fused single-head logits (head spans NTILE cols)
//      6 (+bias) + fused row L2-normalize -> C
// SPLITA: A is fp32 (passed via Ahi); split hi/lo on the fly in the loader.
template <int NTILE, int EPI, bool SPLITA>
__global__ void __launch_bounds__(512, 1) mm_mma(
    const __nv_bfloat16* __restrict__ Ahi, const __nv_bfloat16* __restrict__ Alo,
    const __nv_bfloat16* __restrict__ Bhi, const __nv_bfloat16* __restrict__ Blo,
    const float* __restrict__ bias, float* __restrict__ C,
    __nv_bfloat16* __restrict__ Chi, __nv_bfloat16* __restrict__ Clo,
    const float* __restrict__ aS, const float* __restrict__ aD,
    float* __restrict__ alsOut, float* __restrict__ aldOut,
    int M, int K)
{
    constexpr int LDE = 72;
    constexpr int A_EL = 128 * LDE;
    constexpr int B_EL = NTILE * LDE;
    constexpr int OFF_AHI = 0;
    constexpr int OFF_ALO = A_EL;
    constexpr int OFF_BHI = 2 * A_EL;
    constexpr int OFF_BLO = 2 * A_EL + B_EL;
    constexpr int STAGE = 2 * A_EL + 2 * B_EL;
    constexpr int WN  = NTILE / 4;   // warp col width
    constexpr int NTL = NTILE / 32;  // 8-col tiles per warp (8 or 4)

    extern __shared__ __nv_bfloat16 sm[];
    const uint32_t sm_base = smem_u32(sm);

    const int tid  = threadIdx.x;
    const int wid  = tid >> 5;
    const int lane = tid & 31;
    const int wm   = wid & 3;     // 4 row groups of 32
    const int wn   = wid >> 2;    // 4 col groups of WN
    const int m0   = blockIdx.y * 128;
    const int nk   = K >> 6;

    const int l7 = lane & 7;
    const int a_rq = ((lane >> 3) & 1) * 8;
    const int a_kq = (lane >> 4) * 8;
    const int b_rq = (lane >> 4) * 8;
    const int b_kq = ((lane >> 3) & 1) * 8;

    float4 acc[2][NTL];
    #pragma unroll
    for (int i = 0; i < 2; i++)
        #pragma unroll
        for (int j = 0; j < NTL; j++) acc[i][j] = make_float4(0.f, 0.f, 0.f, 0.f);

    // ---- loaders ----
    auto load_b = [&](int kc, int st) {
        const int k0 = kc * 64;
        const uint32_t sb = sm_base + (uint32_t)(st * STAGE) * 2;
        #pragma unroll
        for (int c = 0; c < NTILE / 64; c++) {
            int idx = c * 512 + tid;
            int row = idx >> 3, seg = idx & 7;
            uint32_t doff = (uint32_t)(row * LDE + seg * 8) * 2;
            const size_t goff = (size_t)row * K + k0 + seg * 8;
            cp_async16(sb + OFF_BHI * 2 + doff, &Bhi[goff]);
            cp_async16(sb + OFF_BLO * 2 + doff, &Blo[goff]);
        }
        CP_COMMIT();
    };
    auto load_a_bf16 = [&](int kc, int st) {
        const int k0 = kc * 64;
        const uint32_t sb = sm_base + (uint32_t)(st * STAGE) * 2;
        #pragma unroll
        for (int c = 0; c < 2; c++) {
            int idx = c * 512 + tid;
            int row = idx >> 3, seg = idx & 7;
            uint32_t doff = (uint32_t)(row * LDE + seg * 8) * 2;
            int gm = m0 + row;
            if (gm < M) {
                cp_async16(sb + OFF_AHI * 2 + doff, &Ahi[(size_t)gm * K + k0 + seg * 8]);
                cp_async16(sb + OFF_ALO * 2 + doff, &Alo[(size_t)gm * K + k0 + seg * 8]);
            } else {
                uint4 z = make_uint4(0, 0, 0, 0);
                *(uint4*)(sm + st * STAGE + OFF_AHI + row * LDE + seg * 8) = z;
                *(uint4*)(sm + st * STAGE + OFF_ALO + row * LDE + seg * 8) = z;
            }
        }
    };
    float4 areg[4];
    auto load_a_regs = [&](int kc) {
        const float* Afp = (const float*)Ahi;
        const int k0 = kc * 64;
        #pragma unroll
        for (int c = 0; c < 4; c++) {
            int idx = c * 512 + tid;
            int row = idx >> 4, seg = idx & 15;
            int gm = m0 + row;
            areg[c] = (gm < M) ? *(const float4*)&Afp[(size_t)gm * K + k0 + seg * 4]
                               : make_float4(0.f, 0.f, 0.f, 0.f);
        }
    };
    auto sts_a = [&](int st) {
        #pragma unroll
        for (int c = 0; c < 4; c++) {
            int idx = c * 512 + tid;
            int row = idx >> 4, seg = idx & 15;
            uint32_t h0, l0, h1, l1;
            split2(areg[c].x, areg[c].y, h0, l0);
            split2(areg[c].z, areg[c].w, h1, l1);
            *(uint2*)(sm + st * STAGE + OFF_AHI + row * LDE + seg * 4) = make_uint2(h0, h1);
            *(uint2*)(sm + st * STAGE + OFF_ALO + row * LDE + seg * 4) = make_uint2(l0, l1);
        }
    };

    auto compute = [&](int kc) {
        const uint32_t sst = sm_base + (uint32_t)((kc & 1) * STAGE) * 2;
        #pragma unroll
        for (int kk = 0; kk < 4; kk++) {
            const int k0b = kk * 16;
            uint32_t fahi[2][4], falo[2][4];
            #pragma unroll
            for (int mt = 0; mt < 2; mt++) {
                int arow = wm * 32 + mt * 16 + l7 + a_rq;
                ldsm_x4(fahi[mt][0], fahi[mt][1], fahi[mt][2], fahi[mt][3],
                        sst + (uint32_t)(OFF_AHI + arow * LDE + k0b + a_kq) * 2);
                ldsm_x4(falo[mt][0], falo[mt][1], falo[mt][2], falo[mt][3],
                        sst + (uint32_t)(OFF_ALO + arow * LDE + k0b + a_kq) * 2);
            }
            #pragma unroll
            for (int h = 0; h < NTL / 4; h++) {
                uint32_t fbhi[4][2], fblo[4][2];
                #pragma unroll
                for (int p = 0; p < 2; p++) {
                    int brow = wn * WN + h * 32 + p * 16 + l7 + b_rq;
                    ldsm_x4(fbhi[2*p][0], fbhi[2*p][1], fbhi[2*p+1][0], fbhi[2*p+1][1],
                            sst + (uint32_t)(OFF_BHI + brow * LDE + k0b + b_kq) * 2);
                    ldsm_x4(fblo[2*p][0], fblo[2*p][1], fblo[2*p+1][0], fblo[2*p+1][1],
                            sst + (uint32_t)(OFF_BLO + brow * LDE + k0b + b_kq) * 2);
                }
                #pragma unroll
                for (int mt = 0; mt < 2; mt++)
                    #pragma unroll
                    for (int jj = 0; jj < 4; jj++) {
                        float4& d = acc[mt][h * 4 + jj];
                        MMA_BF16(d, fahi[mt][0], fahi[mt][1], fahi[mt][2], fahi[mt][3],
                                 fbhi[jj][0], fbhi[jj][1]);
                        MMA_BF16(d, fahi[mt][0], fahi[mt][1], fahi[mt][2], fahi[mt][3],
                                 fblo[jj][0], fblo[jj][1]);
                        MMA_BF16(d, falo[mt][0], falo[mt][1], falo[mt][2], falo[mt][3],
                                 fbhi[jj][0], fbhi[jj][1]);
                    }
            }
        }
    };

    // ---- mainloop ----
    if (SPLITA) {
        load_a_regs(0);
        load_b(0, 0);
        for (int kc = 0; kc < nk; kc++) {
            sts_a(kc & 1);
            if (kc + 1 < nk) load_a_regs(kc + 1);
            CP_WAIT0();
            __syncthreads();
            if (kc + 1 < nk) load_b(kc + 1, (kc + 1) & 1);
            compute(kc);
        }
    } else {
        load_a_bf16(0, 0);
        load_b(0, 0);
        for (int kc = 0; kc < nk; kc++) {
            CP_WAIT0();
            __syncthreads();
            if (kc + 1 < nk) { load_a_bf16(kc + 1, (kc + 1) & 1); load_b(kc + 1, (kc + 1) & 1); }
            compute(kc);
        }
    }

    // ---- epilogue ----
    float* sred = (float*)sm;

    if (EPI == 3) {
        #pragma unroll
        for (int mt = 0; mt < 2; mt++) {
            #pragma unroll
            for (int j = 0; j < NTL; j++) {
                float4 d = acc[mt][j];
                int r0  = m0 + wm * 32 + mt * 16 + (lane >> 2);
                int col = wn * WN + j * 8 + (lane & 3) * 2;
                float bv0 = bias[col], bv1 = bias[col + 1];
                d.x = fmaxf(d.x + bv0, 0.f); d.y = fmaxf(d.y + bv1, 0.f);
                d.z = fmaxf(d.z + bv0, 0.f); d.w = fmaxf(d.w + bv1, 0.f);
                uint32_t h, l;
                if (r0 < M) {
                    split2(d.x, d.y, h, l);
                    *(uint32_t*)&Chi[(size_t)r0 * NTILE + col] = h;
                    *(uint32_t*)&Clo[(size_t)r0 * NTILE + col] = l;
                }
                if (r0 + 8 < M) {
                    split2(d.z, d.w, h, l);
                    *(uint32_t*)&Chi[(size_t)(r0 + 8) * NTILE + col] = h;
                    *(uint32_t*)&Clo[(size_t)(r0 + 8) * NTILE + col] = l;
                }
            }
        }
    }

    if (EPI == 4 || EPI == 5) {
        __syncthreads();
        for (int t = tid; t < 1024; t += 512) sred[t] = 0.f;
        __syncthreads();
        #pragma unroll
        for (int mt = 0; mt < 2; mt++) {
            float psA = 0.f, pdA = 0.f, psB = 0.f, pdB = 0.f;
            int lr = wm * 32 + mt * 16 + (lane >> 2);
            #pragma unroll
            for (int j = 0; j < NTL; j++) {
                float4 d = acc[mt][j];
                int col = wn * WN + j * 8 + (lane & 3) * 2;
                int r0 = m0 + lr;
                if (r0 < M)
                    *(float2*)&C[(size_t)r0 * NTILE + col] = make_float2(d.x, d.y);
                if (r0 + 8 < M)
                    *(float2*)&C[(size_t)(r0 + 8) * NTILE + col] = make_float2(d.z, d.w);
                float s0 = aS[col], s1 = aS[col + 1];
                float q0 = aD[col], q1 = aD[col + 1];
                psA += d.x * s0 + d.y * s1;  pdA += d.x * q0 + d.y * q1;
                psB += d.z * s0 + d.w * s1;  pdB += d.z * q0 + d.w * q1;
            }
            #pragma unroll
            for (int o = 1; o <= 2; o <<= 1) {
                psA += __shfl_xor_sync(0xffffffffu, psA, o);
                pdA += __shfl_xor_sync(0xffffffffu, pdA, o);
                psB += __shfl_xor_sync(0xffffffffu, psB, o);
                pdB += __shfl_xor_sync(0xffffffffu, pdB, o);
            }
            if ((lane & 3) == 0) {
                atomicAdd(&sred[lr * 4 + wn], psA);
                atomicAdd(&sred[512 + lr * 4 + wn], pdA);
                atomicAdd(&sred[(lr + 8) * 4 + wn], psB);
                atomicAdd(&sred[512 + (lr + 8) * 4 + wn], pdB);
            }
        }
        __syncthreads();
        if (EPI == 4) {
            // NTILE=256: warp col group == head (WN=64)
            int row = tid >> 2, head = tid & 3;
            int gm = m0 + row;
            if (gm < M) {
                alsOut[(size_t)gm * 4 + head] = sred[tid];
                aldOut[(size_t)gm * 4 + head] = sred[512 + tid];
            }
        } else {
            if (tid < 128) {
                int gm = m0 + tid;
                if (gm < M) {
                    alsOut[gm] = sred[tid*4] + sred[tid*4+1] + sred[tid*4+2] + sred[tid*4+3];
                    aldOut[gm] = sred[512 + tid*4] + sred[512 + tid*4+1]
                               + sred[512 + tid*4+2] + sred[512 + tid*4+3];
                }
            }
        }
    }

    if (EPI == 6) {
        __syncthreads();
        if (tid < 128) sred[tid] = 0.f;
        __syncthreads();
        #pragma unroll
        for (int mt = 0; mt < 2; mt++) {
            float qA = 0.f, qB = 0.f;
            int lr = wm * 32 + mt * 16 + (lane >> 2);
            #pragma unroll
            for (int j = 0; j < NTL; j++) {
                float4& d = acc[mt][j];
                int col = wn * WN + j * 8 + (lane & 3) * 2;
                float bv0 = bias[col], bv1 = bias[col + 1];
                d.x += bv0; d.y += bv1; d.z += bv0; d.w += bv1;
                qA += d.x * d.x + d.y * d.y;
                qB += d.z * d.z + d.w * d.w;
            }
            #pragma unroll
            for (int o = 1; o <= 2; o <<= 1) {
                qA += __shfl_xor_sync(0xffffffffu, qA, o);
                qB += __shfl_xor_sync(0xffffffffu, qB, o);
            }
            if ((lane & 3) == 0) {
                atomicAdd(&sred[lr], qA);
                atomicAdd(&sred[lr + 8], qB);
            }
        }
        __syncthreads();
        #pragma unroll
        for (int mt = 0; mt < 2; mt++) {
            int lr = wm * 32 + mt * 16 + (lane >> 2);
            float scA = 1.0f / fmaxf(sqrtf(sred[lr]), 1e-12f);
            float scB = 1.0f / fmaxf(sqrtf(sred[lr + 8]), 1e-12f);
            #pragma unroll
            for (int j = 0; j < NTL; j++) {
                float4 d = acc[mt][j];
                int col = wn * WN + j * 8 + (lane & 3) * 2;
                int r0 = m0 + lr;
                if (r0 < M)
                    *(float2*)&C[(size_t)r0 * NTILE + col] = make_float2(d.x * scA, d.y * scA);
                if (r0 + 8 < M)
                    *(float2*)&C[(size_t)(r0 + 8) * NTILE + col] = make_float2(d.z * scB, d.w * scB);
            }
        }
    }
}

// ---------------- fused GAT layer 0 ---------------------------------------------
__global__ void gat0_kernel(const int* __restrict__ csrc, const int* __restrict__ off,
                            const int* __restrict__ deg,
                            const float* __restrict__ als, const float* __restrict__ ald,
                            const float* __restrict__ xw,
                            const __nv_bfloat16* __restrict__ hhi,
                            const __nv_bfloat16* __restrict__ hlo,
                            const float* __restrict__ b0, const float* __restrict__ g0,
                            const float* __restrict__ be0,
                            __nv_bfloat16* __restrict__ h1hi, __nv_bfloat16* __restrict__ h1lo,
                            int n)
{
    int d = (blockIdx.x * blockDim.x + threadIdx.x) >> 5;
    int lane = threadIdx.x & 31;
    if (d >= n) return;
    const int head = lane >> 3;
    const float aldv = ald[(size_t)d * 4 + head];

    float ex = expf(lrelu(als[(size_t)d * 4 + head] + aldv));
    const float4* xp = (const float4*)&xw[(size_t)d * 256 + lane * 8];
    float4 A = xp[0], B = xp[1];
    float v[8] = {A.x * ex, A.y * ex, A.z * ex, A.w * ex,
                  B.x * ex, B.y * ex, B.z * ex, B.w * ex};
    float den = ex;

    const int start = off[d];
    const int cnt = deg[d];
    int e = 0;
    for (; e + 4 <= cnt; e += 4) {
        int s0 = csrc[start + e + 0];
        int s1 = csrc[start + e + 1];
        int s2 = csrc[start + e + 2];
        int s3 = csrc[start + e + 3];
        float x0 = als[(size_t)s0 * 4 + head];
        float x1 = als[(size_t)s1 * 4 + head];
        float x2 = als[(size_t)s2 * 4 + head];
        float x3 = als[(size_t)s3 * 4 + head];
        const float4* p0 = (const float4*)&xw[(size_t)s0 * 256 + lane * 8];
        const float4* p1 = (const float4*)&xw[(size_t)s1 * 256 + lane * 8];
        const float4* p2 = (const float4*)&xw[(size_t)s2 * 256 + lane * 8];
        const float4* p3 = (const float4*)&xw[(size_t)s3 * 256 + lane * 8];
        float4 a0 = p0[0], c0 = p0[1];
        float4 a1 = p1[0], c1 = p1[1];
        float4 a2 = p2[0], c2 = p2[1];
        float4 a3 = p3[0], c3 = p3[1];
        float e0 = expf(lrelu(x0 + aldv));
        float e1 = expf(lrelu(x1 + aldv));
        float e2 = expf(lrelu(x2 + aldv));
        float e3 = expf(lrelu(x3 + aldv));
        v[0] = fmaf(a0.x, e0, v[0]); v[1] = fmaf(a0.y, e0, v[1]);
        v[2] = fmaf(a0.z, e0, v[2]); v[3] = fmaf(a0.w, e0, v[3]);
        v[4] = fmaf(c0.x, e0, v[4]); v[5] = fmaf(c0.y, e0, v[5]);
        v[6] = fmaf(c0.z, e0, v[6]); v[7] = fmaf(c0.w, e0, v[7]);
        v[0] = fmaf(a1.x, e1, v[0]); v[1] = fmaf(a1.y, e1, v[1]);
        v[2] = fmaf(a1.z, e1, v[2]); v[3] = fmaf(a1.w, e1, v[3]);
        v[4] = fmaf(c1.x, e1, v[4]); v[5] = fmaf(c1.y, e1, v[5]);
        v[6] = fmaf(c1.z, e1, v[6]); v[7] = fmaf(c1.w, e1, v[7]);
        v[0] = fmaf(a2.x, e2, v[0]); v[1] = fmaf(a2.y, e2, v[1]);
        v[2] = fmaf(a2.z, e2, v[2]); v[3] = fmaf(a2.w, e2, v[3]);
        v[4] = fmaf(c2.x, e2, v[4]); v[5] = fmaf(c2.y, e2, v[5]);
        v[6] = fmaf(c2.z, e2, v[6]); v[7] = fmaf(c2.w, e2, v[7]);
        v[0] = fmaf(a3.x, e3, v[0]); v[1] = fmaf(a3.y, e3, v[1]);
        v[2] = fmaf(a3.z, e3, v[2]); v[3] = fmaf(a3.w, e3, v[3]);
        v[4] = fmaf(c3.x, e3, v[4]); v[5] = fmaf(c3.y, e3, v[5]);
        v[6] = fmaf(c3.z, e3, v[6]); v[7] = fmaf(c3.w, e3, v[7]);
        den += e0 + e1 + e2 + e3;
    }
    for (; e < cnt; e++) {
        int s = csrc[start + e];
        float exe = expf(lrelu(als[(size_t)s * 4 + head] + aldv));
        const float4* sp = (const float4*)&xw[(size_t)s * 256 + lane * 8];
        float4 a = sp[0], b = sp[1];
        v[0] = fmaf(a.x, exe, v[0]); v[1] = fmaf(a.y, exe, v[1]);
        v[2] = fmaf(a.z, exe, v[2]); v[3] = fmaf(a.w, exe, v[3]);
        v[4] = fmaf(b.x, exe, v[4]); v[5] = fmaf(b.y, exe, v[5]);
        v[6] = fmaf(b.z, exe, v[6]); v[7] = fmaf(b.w, exe, v[7]);
        den += exe;
    }

    const float inv = 1.0f / den;
    const int c = lane * 8;
    #pragma unroll
    for (int j = 0; j < 8; j++) v[j] = v[j] * inv + b0[c + j];

    float s = 0.f;
    #pragma unroll
    for (int j = 0; j < 8; j++) s += v[j];
    #pragma unroll
    for (int o = 16; o; o >>= 1) s += __shfl_xor_sync(0xffffffffu, s, o);
    float mu = s * (1.0f / 256.0f);
    float q = 0.f;
    #pragma unroll
    for (int j = 0; j < 8; j++) { float t = v[j] - mu; q += t * t; }
    #pragma unroll
    for (int o = 16; o; o >>= 1) q += __shfl_xor_sync(0xffffffffu, q, o);
    float rs = rsqrtf(q * (1.0f / 256.0f) + 1e-5f);

    uint4 rh = *(const uint4*)&hhi[(size_t)d * 256 + c];
    uint4 rl = *(const uint4*)&hlo[(size_t)d * 256 + c];
    float2 r0 = bf2_to_f2(rh.x), r1 = bf2_to_f2(rh.y), r2 = bf2_to_f2(rh.z), r3 = bf2_to_f2(rh.w);
    float2 l0 = bf2_to_f2(rl.x), l1 = bf2_to_f2(rl.y), l2 = bf2_to_f2(rl.z), l3 = bf2_to_f2(rl.w);
    float res[8] = {r0.x + l0.x, r0.y + l0.y, r1.x + l1.x, r1.y + l1.y,
                    r2.x + l2.x, r2.y + l2.y, r3.x + l3.x, r3.y + l3.y};

    #pragma unroll
    for (int j = 0; j < 8; j++) {
        float y = (v[j] - mu) * rs * g0[c + j] + be0[c + j] + res[j];
        v[j] = fmaxf(y, 0.0f);
    }
    uint32_t hh[4], ll[4];
    #pragma unroll
    for (int p = 0; p < 4; p++) split2(v[2*p], v[2*p+1], hh[p], ll[p]);
    *(uint4*)&h1hi[(size_t)d * 256 + c] = make_uint4(hh[0], hh[1], hh[2], hh[3]);
    *(uint4*)&h1lo[(size_t)d * 256 + c] = make_uint4(ll[0], ll[1], ll[2], ll[3]);
}

// ---------------- fused GAT layer 1 ---------------------------------------------
__global__ void gat1_kernel(const int* __restrict__ csrc, const int* __restrict__ off,
                            const int* __restrict__ deg,
                            const float* __restrict__ als, const float* __restrict__ ald,
                            const float* __restrict__ xw,
                            const float* __restrict__ b1, const float* __restrict__ g1,
                            const float* __restrict__ be1,
                            __nv_bfloat16* __restrict__ h2hi, __nv_bfloat16* __restrict__ h2lo,
                            int n)
{
    int d = (blockIdx.x * blockDim.x + threadIdx.x) >> 5;
    int lane = threadIdx.x & 31;
    if (d >= n) return;
    const float aldv = ald[d];

    float ex = expf(lrelu(als[d] + aldv));
    float4 V = *(const float4*)&xw[(size_t)d * 128 + lane * 4];
    float v[4] = {V.x * ex, V.y * ex, V.z * ex, V.w * ex};
    float den = ex;

    const int start = off[d];
    const int cnt = deg[d];
    int e = 0;
    for (; e + 4 <= cnt; e += 4) {
        int s0 = csrc[start + e + 0];
        int s1 = csrc[start + e + 1];
        int s2 = csrc[start + e + 2];
        int s3 = csrc[start + e + 3];
        float x0 = als[s0], x1 = als[s1], x2 = als[s2], x3 = als[s3];
        float4 a0 = *(const float4*)&xw[(size_t)s0 * 128 + lane * 4];
        float4 a1 = *(const float4*)&xw[(size_t)s1 * 128 + lane * 4];
        float4 a2 = *(const float4*)&xw[(size_t)s2 * 128 + lane * 4];
        float4 a3 = *(const float4*)&xw[(size_t)s3 * 128 + lane * 4];
        float e0 = expf(lrelu(x0 + aldv));
        float e1 = expf(lrelu(x1 + aldv));
        float e2 = expf(lrelu(x2 + aldv));
        float e3 = expf(lrelu(x3 + aldv));
        v[0] = fmaf(a0.x, e0, v[0]); v[1] = fmaf(a0.y, e0, v[1]);
        v[2] = fmaf(a0.z, e0, v[2]); v[3] = fmaf(a0.w, e0, v[3]);
        v[0] = fmaf(a1.x, e1, v[0]); v[1] = fmaf(a1.y, e1, v[1]);
        v[2] = fmaf(a1.z, e1, v[2]); v[3] = fmaf(a1.w, e1, v[3]);
        v[0] = fmaf(a2.x, e2, v[0]); v[1] = fmaf(a2.y, e2, v[1]);
        v[2] = fmaf(a2.z, e2, v[2]); v[3] = fmaf(a2.w, e2, v[3]);
        v[0] = fmaf(a3.x, e3, v[0]); v[1] = fmaf(a3.y, e3, v[1]);
        v[2] = fmaf(a3.z, e3, v[2]); v[3] = fmaf(a3.w, e3, v[3]);
        den += e0 + e1 + e2 + e3;
    }
    for (; e < cnt; e++) {
        int s = csrc[start + e];
        float exe = expf(lrelu(als[s] + aldv));
        float4 a = *(const float4*)&xw[(size_t)s * 128 + lane * 4];
        v[0] = fmaf(a.x, exe, v[0]); v[1] = fmaf(a.y, exe, v[1]);
        v[2] = fmaf(a.z, exe, v[2]); v[3] = fmaf(a.w, exe, v[3]);
        den += exe;
    }

    const float inv = 1.0f / den;
    const int c = lane * 4;
    #pragma unroll
    for (int j = 0; j < 4; j++) v[j] = v[j] * inv + b1[c + j];

    float s = v[0] + v[1] + v[2] + v[3];
    #pragma unroll
    for (int o = 16; o; o >>= 1) s += __shfl_xor_sync(0xffffffffu, s, o);
    float mu = s * (1.0f / 128.0f);
    float q = 0.f;
    #pragma unroll
    for (int j = 0; j < 4; j++) { float t = v[j] - mu; q += t * t; }
    #pragma unroll
    for (int o = 16; o; o >>= 1) q += __shfl_xor_sync(0xffffffffu, q, o);
    float rs = rsqrtf(q * (1.0f / 128.0f) + 1e-5f);

    float y0 = (v[0] - mu) * rs * g1[c + 0] + be1[c + 0];
    float y1 = (v[1] - mu) * rs * g1[c + 1] + be1[c + 1];
    float y2 = (v[2] - mu) * rs * g1[c + 2] + be1[c + 2];
    float y3 = (v[3] - mu) * rs * g1[c + 3] + be1[c + 3];
    uint32_t h0, l0, h1v, l1;
    split2(y0, y1, h0, l0);
    split2(y2, y3, h1v, l1);
    *(uint2*)&h2hi[(size_t)d * 128 + c] = make_uint2(h0, h1v);
    *(uint2*)&h2lo[(size_t)d * 128 + c] = make_uint2(l0, l1);
}

// ---------------- launch ---------------------------------------------------------
static inline int cdiv(int a, int b) { return (a + b - 1) / b; }

extern "C" void kernel_launch(void* const* d_in, const int* in_sizes, int n_in,
                              void* d_out, int out_size)
{
    const float* x   = (const float*)d_in[0];
    const int*   ei  = (const int*)d_in[1];
    const float* Wp  = (const float*)d_in[2];
    const float* bp  = (const float*)d_in[3];
    const float* W0  = (const float*)d_in[4];
    const float* as0 = (const float*)d_in[5];
    const float* ad0 = (const float*)d_in[6];
    const float* b0  = (const float*)d_in[7];
    const float* W1  = (const float*)d_in[8];
    const float* as1 = (const float*)d_in[9];
    const float* ad1 = (const float*)d_in[10];
    const float* b1  = (const float*)d_in[11];
    const float* g0  = (const float*)d_in[12];
    const float* be0 = (const float*)d_in[13];
    const float* g1  = (const float*)d_in[14];
    const float* be1 = (const float*)d_in[15];
    const float* Wo  = (const float*)d_in[16];
    const float* bo  = (const float*)d_in[17];
    float* out = (float*)d_out;

    const int n = in_sizes[0] / DIM_IN;
    const int E = in_sizes[1] / 2;
    const int* src = ei;
    const int* dst = ei + E;

    float *p_xw0, *p_xw1, *p_als0, *p_ald0, *p_als1, *p_ald1;
    int *p_deg, *p_off, *p_cursor, *p_csrc;
    __nv_bfloat16 *p_hhi, *p_hlo, *p_h1hi, *p_h1lo, *p_h2hi, *p_h2lo;
    __nv_bfloat16 *p_WpThi, *p_WpTlo, *p_W0Thi, *p_W0Tlo, *p_W1Thi, *p_W1Tlo, *p_WoThi, *p_WoTlo;
    cudaGetSymbolAddress((void**)&p_xw0,  g_xw0);
    cudaGetSymbolAddress((void**)&p_xw1,  g_xw1);
    cudaGetSymbolAddress((void**)&p_als0, g_als0);
    cudaGetSymbolAddress((void**)&p_ald0, g_ald0);
    cudaGetSymbolAddress((void**)&p_als1, g_als1);
    cudaGetSymbolAddress((void**)&p_ald1, g_ald1);
    cudaGetSymbolAddress((void**)&p_deg,    g_deg);
    cudaGetSymbolAddress((void**)&p_off,    g_off);
    cudaGetSymbolAddress((void**)&p_cursor, g_cursor);
    cudaGetSymbolAddress((void**)&p_csrc,   g_csrc);
    cudaGetSymbolAddress((void**)&p_hhi,  g_hhi);
    cudaGetSymbolAddress((void**)&p_hlo,  g_hlo);
    cudaGetSymbolAddress((void**)&p_h1hi, g_h1hi);
    cudaGetSymbolAddress((void**)&p_h1lo, g_h1lo);
    cudaGetSymbolAddress((void**)&p_h2hi, g_h2hi);
    cudaGetSymbolAddress((void**)&p_h2lo, g_h2lo);
    cudaGetSymbolAddress((void**)&p_WpThi, g_WpThi);
    cudaGetSymbolAddress((void**)&p_WpTlo, g_WpTlo);
    cudaGetSymbolAddress((void**)&p_W0Thi, g_W0Thi);
    cudaGetSymbolAddress((void**)&p_W0Tlo, g_W0Tlo);
    cudaGetSymbolAddress((void**)&p_W1Thi, g_W1Thi);
    cudaGetSymbolAddress((void**)&p_W1Tlo, g_W1Tlo);
    cudaGetSymbolAddress((void**)&p_WoThi, g_WoThi);
    cudaGetSymbolAddress((void**)&p_WoTlo, g_WoTlo);

    constexpr int SM256 = 2 * (2 * 128 * 72 + 2 * 256 * 72) * 2;  // 221184 B
    constexpr int SM128 = 2 * (2 * 128 * 72 + 2 * 128 * 72) * 2;  // 147456 B
    cudaFuncSetAttribute(mm_mma<256, 3, true>,  cudaFuncAttributeMaxDynamicSharedMemorySize, SM256);
    cudaFuncSetAttribute(mm_mma<256, 4, false>, cudaFuncAttributeMaxDynamicSharedMemorySize, SM256);
    cudaFuncSetAttribute(mm_mma<128, 5, false>, cudaFuncAttributeMaxDynamicSharedMemorySize, SM128);
    cudaFuncSetAttribute(mm_mma<128, 6, false>, cudaFuncAttributeMaxDynamicSharedMemorySize, SM128);

    const dim3 blk(256);
    const int nodeWarpBlocks = cdiv(n * 32, 256);
    const int edge4Blocks = cdiv(E / 4 + 1, 256);
    const int mrows = cdiv(n, 128);
    const int TSPLIT_TOT = DIM_IN*DIM_HID + DIM_HID*DIM_HID + DIM_HID*DIM_OUT + DIM_OUT*DIM_OUT;

    // CSR histogram + weight splits (independent of GEMM 1)
    zero_kernel<<<cdiv(n, 256), blk>>>(p_deg, n);
    hist_kernel<<<edge4Blocks, blk>>>(dst, p_deg, E);
    tsplit_all_kernel<<<cdiv(TSPLIT_TOT, 256), blk>>>(
        Wp, p_WpThi, p_WpTlo, W0, p_W0Thi, p_W0Tlo,
        W1, p_W1Thi, p_W1Tlo, Wo, p_WoThi, p_WoTlo);

    // 1) h = relu(x @ Wp + bp) -> bf16 hi/lo (x split fused into the loader)
    mm_mma<256, 3, true><<<dim3(1, mrows), 512, SM256>>>(
        (const __nv_bfloat16*)x, nullptr, p_WpThi, p_WpTlo, bp, nullptr, p_hhi, p_hlo,
        nullptr, nullptr, nullptr, nullptr, n, DIM_IN);

    // finish CSR
    scan_kernel<<<1, 1024>>>(p_deg, p_off, p_cursor, n);
    scatter_kernel<<<edge4Blocks, blk>>>(src, dst, p_cursor, p_csrc, E);

    // 2) xw0 = h @ W0 (fp32) + fused layer-0 logits
    mm_mma<256, 4, false><<<dim3(1, mrows), 512, SM256>>>(
        p_hhi, p_hlo, p_W0Thi, p_W0Tlo, nullptr, p_xw0, nullptr, nullptr,
        as0, ad0, p_als0, p_ald0, n, DIM_HID);
    // 3) fused gather-softmax-LN-residual-relu
    gat0_kernel<<<nodeWarpBlocks, blk>>>(p_csrc, p_off, p_deg, p_als0, p_ald0, p_xw0,
                                         p_hhi, p_hlo, b0, g0, be0, p_h1hi, p_h1lo, n);

    // 4) xw1 = h1 @ W1 + fused layer-1 logits
    mm_mma<128, 5, false><<<dim3(1, mrows), 512, SM128>>>(
        p_h1hi, p_h1lo, p_W1Thi, p_W1Tlo, nullptr, p_xw1, nullptr, nullptr,
        as1, ad1, p_als1, p_ald1, n, DIM_HID);
    // 5) fused layer 1
    gat1_kernel<<<nodeWarpBlocks, blk>>>(p_csrc, p_off, p_deg, p_als1, p_ald1, p_xw1,
                                         b1, g1, be1, p_h2hi, p_h2lo, n);

    // 6) out = normalize(h2 @ Wo + bo)
    mm_mma<128, 6, false><<<dim3(1, mrows), 512, SM128>>>(
        p_h2hi, p_h2lo, p_WoThi, p_WoTlo, bo, out, nullptr, nullptr,
        nullptr, nullptr, nullptr, nullptr, n, DIM_OUT);
}